// round 2
// baseline (speedup 1.0000x reference)
#include <cuda_runtime.h>
#include <math.h>

// Problem dims
#define BSZ 256
#define TT  128
#define FF  512
#define HH  1024
#define G4  4096   // 4*H

// ---------------- scratch (device globals; no allocations allowed) ----------
__device__ float g_xproj[(size_t)BSZ * TT * G4]; // [B*T, 4H] = 536 MB
__device__ float g_gbuf[BSZ * G4];               // per-step gates g = xp + h@R_h
__device__ float g_pf[BSZ * HH];                 // c @ P_f
__device__ float g_pi[BSZ * HH];                 // c @ P_i
__device__ float g_h[BSZ * HH];                  // hidden state
__device__ float g_c[BSZ * HH];                  // cell state

__device__ __forceinline__ float sigm(float v) { return 1.0f / (1.0f + expf(-v)); }

// ---------------- 64x64 tile GEMM core: C(64x64) = A[m0:,:K] * W[:K, n0:] ----
// A: row-major [M, lda] ; W: row-major [K, ldw]. 256 threads, 4x4 per thread.
__device__ __forceinline__ void gemm64x64(
    const float* __restrict__ A, int lda,
    const float* __restrict__ W, int ldw,
    int K, int m0, int n0,
    float (*As)[65], float (*Bs)[64],
    float acc[4][4])
{
    const int tid = threadIdx.x;
    // A tile loader mapping: 64 rows x 16 cols = 256 float4
    const int arow  = tid >> 2;       // 0..63
    const int acolv = tid & 3;        // float4 index 0..3 (cols acolv*4..+3)
    // B tile loader mapping: 16 rows x 64 cols = 256 float4
    const int brow  = tid >> 4;       // 0..15
    const int bcolv = tid & 15;       // float4 index 0..15

    for (int kk = 0; kk < K; kk += 16) {
        float4 av = *reinterpret_cast<const float4*>(
            &A[(size_t)(m0 + arow) * lda + kk + acolv * 4]);
        float4 bv = *reinterpret_cast<const float4*>(
            &W[(size_t)(kk + brow) * ldw + n0 + bcolv * 4]);

        __syncthreads();   // protect previous iteration's reads
        // A stored transposed (k-major) with pad 65 to avoid bank conflicts
        As[acolv * 4 + 0][arow] = av.x;
        As[acolv * 4 + 1][arow] = av.y;
        As[acolv * 4 + 2][arow] = av.z;
        As[acolv * 4 + 3][arow] = av.w;
        *reinterpret_cast<float4*>(&Bs[brow][bcolv * 4]) = bv;
        __syncthreads();

        const int tx = tid & 15;   // output col group
        const int ty = tid >> 4;   // output row group
#pragma unroll
        for (int k = 0; k < 16; k++) {
            float a0 = As[k][ty * 4 + 0];
            float a1 = As[k][ty * 4 + 1];
            float a2 = As[k][ty * 4 + 2];
            float a3 = As[k][ty * 4 + 3];
            float4 b = *reinterpret_cast<float4*>(&Bs[k][tx * 4]);
            acc[0][0] += a0 * b.x; acc[0][1] += a0 * b.y; acc[0][2] += a0 * b.z; acc[0][3] += a0 * b.w;
            acc[1][0] += a1 * b.x; acc[1][1] += a1 * b.y; acc[1][2] += a1 * b.z; acc[1][3] += a1 * b.w;
            acc[2][0] += a2 * b.x; acc[2][1] += a2 * b.y; acc[2][2] += a2 * b.z; acc[2][3] += a2 * b.w;
            acc[3][0] += a3 * b.x; acc[3][1] += a3 * b.y; acc[3][2] += a3 * b.z; acc[3][3] += a3 * b.w;
        }
    }
}

// ---------------- kernels ---------------------------------------------------

// zero h, c
__global__ void k_init()
{
    int idx = blockIdx.x * blockDim.x + threadIdx.x;
    if (idx < BSZ * HH) { g_h[idx] = 0.0f; g_c[idx] = 0.0f; }
}

// x_proj = x @ W_x + b    (M = B*T = 32768, K = F = 512, N = 4H = 4096)
__global__ void k_xproj(const float* __restrict__ x,
                        const float* __restrict__ Wx,
                        const float* __restrict__ bias)
{
    __shared__ float As[16][65];
    __shared__ float Bs[16][64];
    float acc[4][4] = {};
    const int m0 = blockIdx.y * 64;
    const int n0 = blockIdx.x * 64;
    gemm64x64(x, FF, Wx, G4, FF, m0, n0, As, Bs, acc);

    const int tx = threadIdx.x & 15, ty = threadIdx.x >> 4;
    const int colb = n0 + tx * 4;
    float4 bb = *reinterpret_cast<const float4*>(&bias[colb]);
#pragma unroll
    for (int i = 0; i < 4; i++) {
        int row = m0 + ty * 4 + i;
        float4 v = make_float4(acc[i][0] + bb.x, acc[i][1] + bb.y,
                               acc[i][2] + bb.z, acc[i][3] + bb.w);
        *reinterpret_cast<float4*>(&g_xproj[(size_t)row * G4 + colb]) = v;
    }
}

// Phase A per step:
//  z=0: g_gbuf = xp_t + h @ R_h    (N = 4096)
//  z=1: g_pf   = c @ P_f           (N = 1024)
//  z=2: g_pi   = c @ P_i           (N = 1024)
__global__ void k_phaseA(const float* __restrict__ Rh,
                         const float* __restrict__ Pf,
                         const float* __restrict__ Pi,
                         int t)
{
    const int z = blockIdx.z;
    if (z > 0 && blockIdx.x >= 16) return;   // peephole jobs only span N=1024

    __shared__ float As[16][65];
    __shared__ float Bs[16][64];
    float acc[4][4] = {};

    const float* A;
    const float* W;
    int ldw;
    if (z == 0)      { A = g_h; W = Rh; ldw = G4; }
    else if (z == 1) { A = g_c; W = Pf; ldw = HH; }
    else             { A = g_c; W = Pi; ldw = HH; }

    const int m0 = blockIdx.y * 64;
    const int n0 = blockIdx.x * 64;
    gemm64x64(A, HH, W, ldw, HH, m0, n0, As, Bs, acc);

    const int tx = threadIdx.x & 15, ty = threadIdx.x >> 4;
    const int colb = n0 + tx * 4;
#pragma unroll
    for (int i = 0; i < 4; i++) {
        int row = m0 + ty * 4 + i;
        if (z == 0) {
            float4 xp = *reinterpret_cast<const float4*>(
                &g_xproj[((size_t)row * TT + t) * G4 + colb]);
            float4 v = make_float4(acc[i][0] + xp.x, acc[i][1] + xp.y,
                                   acc[i][2] + xp.z, acc[i][3] + xp.w);
            *reinterpret_cast<float4*>(&g_gbuf[(size_t)row * G4 + colb]) = v;
        } else {
            float* out = (z == 1) ? g_pf : g_pi;
            float4 v = make_float4(acc[i][0], acc[i][1], acc[i][2], acc[i][3]);
            *reinterpret_cast<float4*>(&out[(size_t)row * HH + colb]) = v;
        }
    }
}

// cell update: f = sig(gf + pf), i = sig(gi + pi), c = c*f + tanh(gc)*i
__global__ void k_cell()
{
    int idx = blockIdx.x * blockDim.x + threadIdx.x;
    if (idx >= BSZ * HH) return;
    int b = idx >> 10;          // /1024
    int j = idx & 1023;
    const float* gr = &g_gbuf[(size_t)b * G4];
    float f = sigm(gr[j]            + g_pf[idx]);
    float i = sigm(gr[HH + j]       + g_pi[idx]);
    float ct = tanhf(gr[2 * HH + j]);
    g_c[idx] = g_c[idx] * f + ct * i;
}

// Phase B: po = c_new @ P_o ; o = sig(go + po) ; h = tanh(c_new) * o
__global__ void k_phaseB(const float* __restrict__ Po,
                         float* __restrict__ dout,
                         int is_last)
{
    __shared__ float As[16][65];
    __shared__ float Bs[16][64];
    float acc[4][4] = {};
    const int m0 = blockIdx.y * 64;
    const int n0 = blockIdx.x * 64;
    gemm64x64(g_c, HH, Po, HH, HH, m0, n0, As, Bs, acc);

    float* hout = is_last ? dout : g_h;
    const int tx = threadIdx.x & 15, ty = threadIdx.x >> 4;
    const int colb = n0 + tx * 4;
#pragma unroll
    for (int i = 0; i < 4; i++) {
        int row = m0 + ty * 4 + i;
        float4 cnv = *reinterpret_cast<const float4*>(&g_c[(size_t)row * HH + colb]);
        float4 gov = *reinterpret_cast<const float4*>(&g_gbuf[(size_t)row * G4 + 3 * HH + colb]);
        float4 v;
        v.x = tanhf(cnv.x) * sigm(gov.x + acc[i][0]);
        v.y = tanhf(cnv.y) * sigm(gov.y + acc[i][1]);
        v.z = tanhf(cnv.z) * sigm(gov.z + acc[i][2]);
        v.w = tanhf(cnv.w) * sigm(gov.w + acc[i][3]);
        *reinterpret_cast<float4*>(&hout[(size_t)row * HH + colb]) = v;
    }
}

// ---------------- launch -----------------------------------------------------
extern "C" void kernel_launch(void* const* d_in, const int* in_sizes, int n_in,
                              void* d_out, int out_size)
{
    const float* x  = (const float*)d_in[0];
    const float* Wx = (const float*)d_in[1];
    const float* b  = (const float*)d_in[2];
    const float* Rh = (const float*)d_in[3];
    const float* Pf = (const float*)d_in[4];
    const float* Pi = (const float*)d_in[5];
    const float* Po = (const float*)d_in[6];
    float* out = (float*)d_out;

    (void)in_sizes; (void)n_in; (void)out_size;

    // zero h, c
    const int nElem = BSZ * HH;
    k_init<<<(nElem + 511) / 512, 512>>>();

    // hoisted input projection: [B*T, 4H]
    k_xproj<<<dim3(G4 / 64, (BSZ * TT) / 64), 256>>>(x, Wx, b);

    // serial recurrence
    for (int t = 0; t < TT; t++) {
        k_phaseA<<<dim3(G4 / 64, BSZ / 64, 3), 256>>>(Rh, Pf, Pi, t);
        k_cell<<<(nElem + 511) / 512, 512>>>();
        k_phaseB<<<dim3(HH / 64, BSZ / 64), 256>>>(Po, out, (t == TT - 1) ? 1 : 0);
    }
}